// round 10
// baseline (speedup 1.0000x reference)
#include <cuda_runtime.h>
#include <cuda_bf16.h>
#include <cstdint>

#define CDIM 128
#define NS1 148
#define PQ 72   // bf16 tile pitch (144B) for 64-wide tiles: conflict-free LDSM
#define PQA 40  // bf16 tile pitch (80B) for 32-wide tiles: conflict-free LDSM

__device__ float g_part[2][NS1][64][CDIM];   // 9.7 MB
__device__ float g_UV[2][64][CDIM];
__device__ unsigned short g_Ph[64][128], g_Pl[64][128];
__device__ unsigned short g_Rh[64][128], g_Rl[64][128];

// ---------------------------------------------------------------------------
// helpers
// ---------------------------------------------------------------------------
__device__ __forceinline__ unsigned sadr(const void* p) {
    return (unsigned)__cvta_generic_to_shared(p);
}
__device__ __forceinline__ uint32_t pk2(float x0, float x1) {
    uint32_t d;
    asm("cvt.rn.bf16x2.f32 %0, %2, %1;" : "=r"(d) : "f"(x0), "f"(x1));
    return d;
}
__device__ __forceinline__ float bfr(float x) {
    return __bfloat162float(__float2bfloat16(x));
}
__device__ __forceinline__ void cvst(unsigned short* hp, unsigned short* lp, float4 a) {
    ((uint32_t*)hp)[0] = pk2(a.x, a.y);
    ((uint32_t*)hp)[1] = pk2(a.z, a.w);
    float l0 = a.x - bfr(a.x), l1 = a.y - bfr(a.y);
    float l2 = a.z - bfr(a.z), l3 = a.w - bfr(a.w);
    ((uint32_t*)lp)[0] = pk2(l0, l1);
    ((uint32_t*)lp)[1] = pk2(l2, l3);
}
__device__ __forceinline__ void ldmA(uint32_t* a, unsigned addr) {
    asm volatile("ldmatrix.sync.aligned.m8n8.x4.shared.b16 {%0,%1,%2,%3},[%4];"
        : "=r"(a[0]), "=r"(a[1]), "=r"(a[2]), "=r"(a[3]) : "r"(addr));
}
__device__ __forceinline__ void ldmAT(uint32_t* a, unsigned addr) {
    asm volatile("ldmatrix.sync.aligned.m8n8.x4.trans.shared.b16 {%0,%1,%2,%3},[%4];"
        : "=r"(a[0]), "=r"(a[1]), "=r"(a[2]), "=r"(a[3]) : "r"(addr));
}
__device__ __forceinline__ void ldmBT(uint32_t* b, unsigned addr) {
    asm volatile("ldmatrix.sync.aligned.m8n8.x2.trans.shared.b16 {%0,%1},[%2];"
        : "=r"(b[0]), "=r"(b[1]) : "r"(addr));
}
__device__ __forceinline__ void mma(float* d, const uint32_t* a, const uint32_t* b) {
    asm volatile("mma.sync.aligned.m16n8k16.row.col.f32.bf16.bf16.f32 "
        "{%0,%1,%2,%3},{%4,%5,%6,%7},{%8,%9},{%0,%1,%2,%3};"
        : "+f"(d[0]), "+f"(d[1]), "+f"(d[2]), "+f"(d[3])
        : "r"(a[0]), "r"(a[1]), "r"(a[2]), "r"(a[3]), "r"(b[0]), "r"(b[1]));
}
#define NEG4(dst, src) { dst[0]=src[0]^0x80008000u; dst[1]=src[1]^0x80008000u; \
                         dst[2]=src[2]^0x80008000u; dst[3]=src[3]^0x80008000u; }

// ---------------------------------------------------------------------------
// Kernel 1: U/V partials, chunk loop with register prefetch.
// grid (NS1=148, 2 c-halves) = 296 CTAs (2/SM), block 256:
// 8 warps = 4 k-slabs(16) x 2 c-sub(32). Chunk ci = s + t*NS1.
// ---------------------------------------------------------------------------
__global__ __launch_bounds__(256, 2) void k1_partial(
    const float* __restrict__ Qr, const float* __restrict__ Qi,
    const float* __restrict__ re, const float* __restrict__ im, int N)
{
    __shared__ unsigned short sQrh[32][PQ], sQrl[32][PQ], sQih[32][PQ], sQil[32][PQ];
    __shared__ unsigned short sXrh[32][PQ], sXrl[32][PQ], sXih[32][PQ], sXil[32][PQ];

    const int s  = blockIdx.x;
    const int c0 = blockIdx.y * 64;
    const int tid = threadIdx.x;
    const int nchunks = (N + 31) >> 5;
    const float4 f4z = make_float4(0.f, 0.f, 0.f, 0.f);

    const int lane = tid & 31, warp = tid >> 5;
    const int m0 = (warp & 3) * 16;        // k-slab
    const int cs = (warp >> 2) * 32;       // c-sub
    const int r8 = lane & 7, sel = lane >> 3;
    const int atrow = ((sel >> 1) & 1) * 8 + r8;
    const int atcol = m0 + (sel & 1) * 8;
    const int brow = lane & 15;
    const int gid = lane >> 2, tig = lane & 3;

    float u[4][4] = {};
    float v[4][4] = {};

    float4 qa[2], qb[2], xa[2], xb[2];
    auto ldchunk = [&](int ci) {
        #pragma unroll
        for (int q = 0; q < 2; q++) {
            int f = tid + 256 * q;
            int row = f >> 4, k4 = (f & 15) * 4;
            int n = ci * 32 + row;
            bool ok = (n < N);
            qa[q] = ok ? *(const float4*)(Qr + (long)n * 64 + k4) : f4z;
            qb[q] = ok ? *(const float4*)(Qi + (long)n * 64 + k4) : f4z;
            xa[q] = ok ? *(const float4*)(re + (long)n * 128 + c0 + k4) : f4z;
            xb[q] = ok ? *(const float4*)(im + (long)n * 128 + c0 + k4) : f4z;
        }
    };

    if (s < nchunks) ldchunk(s);
    for (int t = 0;; t++) {
        int ci = s + t * NS1;
        if (ci >= nchunks) break;                     // CTA-uniform
        #pragma unroll
        for (int q = 0; q < 2; q++) {
            int f = tid + 256 * q;
            int row = f >> 4, k4 = (f & 15) * 4;
            cvst(&sQrh[row][k4], &sQrl[row][k4], qa[q]);
            cvst(&sQih[row][k4], &sQil[row][k4], qb[q]);
            cvst(&sXrh[row][k4], &sXrl[row][k4], xa[q]);
            cvst(&sXih[row][k4], &sXil[row][k4], xb[q]);
        }
        __syncthreads();
        int cin = ci + NS1;
        if (cin < nchunks) ldchunk(cin);              // prefetch under MMA

        #pragma unroll
        for (int ks = 0; ks < 2; ks++) {
            const int n0k = ks * 16;
            uint32_t qrh[4], qrl[4], qih[4], qil[4], nqh[4], nql[4];
            ldmAT(qrh, sadr(&sQrh[n0k + atrow][atcol]));
            ldmAT(qrl, sadr(&sQrl[n0k + atrow][atcol]));
            ldmAT(qih, sadr(&sQih[n0k + atrow][atcol]));
            ldmAT(qil, sadr(&sQil[n0k + atrow][atcol]));
            NEG4(nqh, qrh);
            NEG4(nql, qrl);
            #pragma unroll
            for (int nt = 0; nt < 4; nt++) {
                uint32_t xh[2], xl[2], yh[2], yl[2];
                ldmBT(xh, sadr(&sXrh[n0k + brow][cs + nt * 8]));
                ldmBT(xl, sadr(&sXrl[n0k + brow][cs + nt * 8]));
                ldmBT(yh, sadr(&sXih[n0k + brow][cs + nt * 8]));
                ldmBT(yl, sadr(&sXil[n0k + brow][cs + nt * 8]));
                mma(u[nt], qrh, xh); mma(u[nt], qrh, xl); mma(u[nt], qrl, xh);
                mma(u[nt], qih, yh); mma(u[nt], qih, yl); mma(u[nt], qil, yh);
                mma(v[nt], qih, xh); mma(v[nt], qih, xl); mma(v[nt], qil, xh);
                mma(v[nt], nqh, yh); mma(v[nt], nqh, yl); mma(v[nt], nql, yh);
            }
        }
        __syncthreads();
    }

    #pragma unroll
    for (int nt = 0; nt < 4; nt++) {
        int k = m0 + gid;
        int c = c0 + cs + nt * 8 + tig * 2;
        *(float2*)&g_part[0][s][k][c]     = make_float2(u[nt][0], u[nt][1]);
        *(float2*)&g_part[0][s][k + 8][c] = make_float2(u[nt][2], u[nt][3]);
        *(float2*)&g_part[1][s][k][c]     = make_float2(v[nt][0], v[nt][1]);
        *(float2*)&g_part[1][s][k + 8][c] = make_float2(v[nt][2], v[nt][3]);
    }
}

// ---------------------------------------------------------------------------
// Kernel 2a: reduce partials over splits, scale row k by TT = Ritz[k]^ld.
// ---------------------------------------------------------------------------
__global__ __launch_bounds__(256) void k2a_reduce(
    const float* __restrict__ Ritz, const int* __restrict__ ldp, int nsplit)
{
    __shared__ float red[256];
    const int o   = threadIdx.x & 31;
    const int seg = threadIdx.x >> 5;
    const int t   = blockIdx.x * 32 + o;       // 0..16383
    const int uv  = t >> 13;
    const int rem = t & 8191;

    const float* p = &g_part[uv][0][0][0] + rem;
    float sum = 0.f;
    for (int s2 = seg; s2 < nsplit; s2 += 8) sum += p[(long)s2 * 8192];
    red[threadIdx.x] = sum;
    __syncthreads();

    if (threadIdx.x < 32) {
        #pragma unroll
        for (int g = 1; g < 8; g++) sum += red[g * 32 + o];
        int k = rem >> 7;
        int ld = *ldp;
        float rz = Ritz[k];
        float tt = 1.f;
        for (int i = 0; i < ld; i++) tt *= rz;
        (&g_UV[0][0][0])[t] = tt * sum;
    }
}

// ---------------------------------------------------------------------------
// Kernel 2b: P = U' @ W, R = V' @ W  ([64,128]@[128,128]); bf16 hi/lo outputs.
// ---------------------------------------------------------------------------
__global__ __launch_bounds__(256) void k2b_pr(const float* __restrict__ W)
{
    __shared__ float sA[64 * 68];
    __shared__ float sW[64 * 64];

    const int m   = blockIdx.x;
    const int cp0 = blockIdx.y * 64;
    const int tx = threadIdx.x, ty = threadIdx.y;
    const int tid = ty * 16 + tx;

    float acc[4][4] = {};

    for (int cc = 0; cc < 128; cc += 64) {
        #pragma unroll
        for (int q = 0; q < 4; q++) {
            int f   = tid + 256 * q;
            int row = f >> 4;
            int c4  = (f & 15) * 4;
            *(float4*)&sA[row * 68 + c4] = *(const float4*)&g_UV[m][row][cc + c4];
            *(float4*)&sW[row * 64 + c4] = *(const float4*)(W + (cc + row) * 128 + cp0 + c4);
        }
        __syncthreads();

        #pragma unroll 4
        for (int r = 0; r < 64; r++) {
            float a[4];
            #pragma unroll
            for (int i = 0; i < 4; i++) a[i] = sA[(ty * 4 + i) * 68 + r];
            float4 w4 = *(float4*)&sW[r * 64 + tx * 4];
            float wj[4] = {w4.x, w4.y, w4.z, w4.w};
            #pragma unroll
            for (int i = 0; i < 4; i++)
                #pragma unroll
                for (int j = 0; j < 4; j++)
                    acc[i][j] += a[i] * wj[j];
        }
        __syncthreads();
    }

    unsigned short (*Dh)[128] = (m == 0) ? g_Ph : g_Rh;
    unsigned short (*Dl)[128] = (m == 0) ? g_Pl : g_Rl;
    #pragma unroll
    for (int i = 0; i < 4; i++) {
        int k = ty * 4 + i;
        int c = cp0 + tx * 4;
        ((uint32_t*)&Dh[k][c])[0] = pk2(acc[i][0], acc[i][1]);
        ((uint32_t*)&Dh[k][c])[1] = pk2(acc[i][2], acc[i][3]);
        float l0 = acc[i][0] - bfr(acc[i][0]), l1 = acc[i][1] - bfr(acc[i][1]);
        float l2 = acc[i][2] - bfr(acc[i][2]), l3 = acc[i][3] - bfr(acc[i][3]);
        ((uint32_t*)&Dl[k][c])[0] = pk2(l0, l1);
        ((uint32_t*)&Dl[k][c])[1] = pk2(l2, l3);
    }
}

// ---------------------------------------------------------------------------
// Kernel 3: res_real = Qr@P + Qi@R, res_imag = Qi@P - Qr@R (MMA 3-pass),
// masked-ReLU epilogue. grid (ceil(N/64), 2 c-halves), block 256:
// 8 warps = 4 n-slabs(16) x 2 c-sub(32). Two k-phases of 32.
// ---------------------------------------------------------------------------
__global__ __launch_bounds__(256, 2) void k3_out(
    const float* __restrict__ Qr, const float* __restrict__ Qi,
    const float* __restrict__ re, const float* __restrict__ im,
    float* __restrict__ out, int N)
{
    __shared__ unsigned short sQrh[64][PQA], sQrl[64][PQA], sQih[64][PQA], sQil[64][PQA];
    __shared__ unsigned short sPh[32][PQ], sPl[32][PQ], sRh[32][PQ], sRl[32][PQ];

    const int n0 = blockIdx.x * 64;
    const int c0 = blockIdx.y * 64;
    const int tid = threadIdx.x;
    const float4 f4z = make_float4(0.f, 0.f, 0.f, 0.f);

    const int lane = tid & 31, warp = tid >> 5;
    const int m0 = (warp & 3) * 16;           // n-slab
    const int cs = (warp >> 2) * 32;          // c-sub
    const int arow = m0 + (lane & 15);
    const int acol8 = (lane >> 4) * 8;
    const int brow = lane & 15;
    const int gid = lane >> 2, tig = lane & 3;

    float sr[4][4] = {};
    float si[4][4] = {};

    #pragma unroll
    for (int ph = 0; ph < 2; ph++) {
        const int kk = ph * 32;
        // batched reg-first loads: Q k-half (fp32->convert) + P/R k-half (bf16)
        float4 qa[2], qb[2];
        uint4 pv, plv, rv, rlv;
        #pragma unroll
        for (int q = 0; q < 2; q++) {
            int f = tid + 256 * q;
            int row = f >> 3, k4 = (f & 7) * 4;
            int n = n0 + row;
            bool ok = (n < N);
            qa[q] = ok ? *(const float4*)(Qr + (long)n * 64 + kk + k4) : f4z;
            qb[q] = ok ? *(const float4*)(Qi + (long)n * 64 + kk + k4) : f4z;
        }
        {
            int row = tid >> 3, cu = tid & 7;
            pv  = *(const uint4*)&g_Ph[kk + row][c0 + cu * 8];
            plv = *(const uint4*)&g_Pl[kk + row][c0 + cu * 8];
            rv  = *(const uint4*)&g_Rh[kk + row][c0 + cu * 8];
            rlv = *(const uint4*)&g_Rl[kk + row][c0 + cu * 8];
        }
        if (ph) __syncthreads();   // protect previous phase reads before overwrite
        #pragma unroll
        for (int q = 0; q < 2; q++) {
            int f = tid + 256 * q;
            int row = f >> 3, k4 = (f & 7) * 4;
            cvst(&sQrh[row][k4], &sQrl[row][k4], qa[q]);
            cvst(&sQih[row][k4], &sQil[row][k4], qb[q]);
        }
        {
            int row = tid >> 3, cu = tid & 7;
            *(uint4*)&sPh[row][cu * 8] = pv;
            *(uint4*)&sPl[row][cu * 8] = plv;
            *(uint4*)&sRh[row][cu * 8] = rv;
            *(uint4*)&sRl[row][cu * 8] = rlv;
        }
        __syncthreads();

        #pragma unroll
        for (int ks = 0; ks < 2; ks++) {
            const int k0 = ks * 16;
            uint32_t qrh[4], qrl[4], qih[4], qil[4], nqh[4], nql[4];
            ldmA(qrh, sadr(&sQrh[arow][k0 + acol8]));
            ldmA(qrl, sadr(&sQrl[arow][k0 + acol8]));
            ldmA(qih, sadr(&sQih[arow][k0 + acol8]));
            ldmA(qil, sadr(&sQil[arow][k0 + acol8]));
            NEG4(nqh, qrh);
            NEG4(nql, qrl);
            #pragma unroll
            for (int nt = 0; nt < 4; nt++) {
                uint32_t pf[2], pl[2], rf[2], rl2[2];
                ldmBT(pf,  sadr(&sPh[k0 + brow][cs + nt * 8]));
                ldmBT(pl,  sadr(&sPl[k0 + brow][cs + nt * 8]));
                ldmBT(rf,  sadr(&sRh[k0 + brow][cs + nt * 8]));
                ldmBT(rl2, sadr(&sRl[k0 + brow][cs + nt * 8]));
                mma(sr[nt], qrh, pf);  mma(sr[nt], qrh, pl);  mma(sr[nt], qrl, pf);
                mma(sr[nt], qih, rf);  mma(sr[nt], qih, rl2); mma(sr[nt], qil, rf);
                mma(si[nt], qih, pf);  mma(si[nt], qih, pl);  mma(si[nt], qil, pf);
                mma(si[nt], nqh, rf);  mma(si[nt], nqh, rl2); mma(si[nt], nql, rf);
            }
        }
    }

    // epilogue: masked-ReLU add, write out
    const long NC = (long)N * 128;
    #pragma unroll
    for (int nt = 0; nt < 4; nt++) {
        int c = c0 + cs + nt * 8 + tig * 2;
        int r0 = n0 + m0 + gid;
        int r1 = r0 + 8;
        if (r0 < N) {
            long base = (long)r0 * 128 + c;
            float2 rvv = *(const float2*)(re + base);
            float2 ivv = *(const float2*)(im + base);
            float mk0 = (sr[nt][0] >= 0.f) ? 1.f : 0.f;
            float mk1 = (sr[nt][1] >= 0.f) ? 1.f : 0.f;
            *(float2*)(out + base)      = make_float2(rvv.x + mk0 * sr[nt][0], rvv.y + mk1 * sr[nt][1]);
            *(float2*)(out + NC + base) = make_float2(ivv.x + mk0 * si[nt][0], ivv.y + mk1 * si[nt][1]);
        }
        if (r1 < N) {
            long base = (long)r1 * 128 + c;
            float2 rvv = *(const float2*)(re + base);
            float2 ivv = *(const float2*)(im + base);
            float mk2 = (sr[nt][2] >= 0.f) ? 1.f : 0.f;
            float mk3 = (sr[nt][3] >= 0.f) ? 1.f : 0.f;
            *(float2*)(out + base)      = make_float2(rvv.x + mk2 * sr[nt][2], rvv.y + mk3 * sr[nt][3]);
            *(float2*)(out + NC + base) = make_float2(ivv.x + mk2 * si[nt][2], ivv.y + mk3 * si[nt][3]);
        }
    }
}

// ---------------------------------------------------------------------------
extern "C" void kernel_launch(void* const* d_in, const int* in_sizes, int n_in,
                              void* d_out, int out_size)
{
    const float* real  = (const float*)d_in[0];
    const float* imag  = (const float*)d_in[1];
    const float* Qreal = (const float*)d_in[2];
    const float* Qimag = (const float*)d_in[3];
    const float* Ritz  = (const float*)d_in[4];
    const float* W     = (const float*)d_in[5];
    const int*   ldp   = (const int*)d_in[6];
    float* out = (float*)d_out;

    int N = in_sizes[0] / CDIM;
    int nchunks = (N + 31) / 32;
    int nsplit = (nchunks < NS1) ? nchunks : NS1;

    k1_partial<<<dim3(NS1, 2), 256>>>(Qreal, Qimag, real, imag, N);
    k2a_reduce<<<512, 256>>>(Ritz, ldp, nsplit);
    k2b_pr<<<dim3(2, 2), dim3(16, 16)>>>(W);
    k3_out<<<dim3((N + 63) / 64, 2), 256>>>(Qreal, Qimag, real, imag, out, N);
}

// round 11
// speedup vs baseline: 1.0653x; 1.0653x over previous
#include <cuda_runtime.h>
#include <cuda_bf16.h>
#include <cstdint>

#define CDIM 128
#define NS1 74
#define PQ 72   // bf16 tile pitch (144B): conflict-free LDSM

__device__ float g_part[2][80][64][CDIM];   // 5.2 MB
__device__ float g_UV[2][64][CDIM];
__device__ unsigned short g_Ph[64][128], g_Pl[64][128];
__device__ unsigned short g_Rh[64][128], g_Rl[64][128];

// ---------------------------------------------------------------------------
// helpers
// ---------------------------------------------------------------------------
__device__ __forceinline__ unsigned sadr(const void* p) {
    return (unsigned)__cvta_generic_to_shared(p);
}
__device__ __forceinline__ uint32_t pk2(float x0, float x1) {
    uint32_t d;
    asm("cvt.rn.bf16x2.f32 %0, %2, %1;" : "=r"(d) : "f"(x0), "f"(x1));
    return d;
}
__device__ __forceinline__ float bfr(float x) {
    return __bfloat162float(__float2bfloat16(x));
}
__device__ __forceinline__ void cvst(unsigned short* hp, unsigned short* lp, float4 a) {
    ((uint32_t*)hp)[0] = pk2(a.x, a.y);
    ((uint32_t*)hp)[1] = pk2(a.z, a.w);
    float l0 = a.x - bfr(a.x), l1 = a.y - bfr(a.y);
    float l2 = a.z - bfr(a.z), l3 = a.w - bfr(a.w);
    ((uint32_t*)lp)[0] = pk2(l0, l1);
    ((uint32_t*)lp)[1] = pk2(l2, l3);
}
__device__ __forceinline__ void ldmA(uint32_t* a, unsigned addr) {
    asm volatile("ldmatrix.sync.aligned.m8n8.x4.shared.b16 {%0,%1,%2,%3},[%4];"
        : "=r"(a[0]), "=r"(a[1]), "=r"(a[2]), "=r"(a[3]) : "r"(addr));
}
__device__ __forceinline__ void ldmAT(uint32_t* a, unsigned addr) {
    asm volatile("ldmatrix.sync.aligned.m8n8.x4.trans.shared.b16 {%0,%1,%2,%3},[%4];"
        : "=r"(a[0]), "=r"(a[1]), "=r"(a[2]), "=r"(a[3]) : "r"(addr));
}
__device__ __forceinline__ void ldmBT(uint32_t* b, unsigned addr) {
    asm volatile("ldmatrix.sync.aligned.m8n8.x2.trans.shared.b16 {%0,%1},[%2];"
        : "=r"(b[0]), "=r"(b[1]) : "r"(addr));
}
__device__ __forceinline__ void mma(float* d, const uint32_t* a, const uint32_t* b) {
    asm volatile("mma.sync.aligned.m16n8k16.row.col.f32.bf16.bf16.f32 "
        "{%0,%1,%2,%3},{%4,%5,%6,%7},{%8,%9},{%0,%1,%2,%3};"
        : "+f"(d[0]), "+f"(d[1]), "+f"(d[2]), "+f"(d[3])
        : "r"(a[0]), "r"(a[1]), "r"(a[2]), "r"(a[3]), "r"(b[0]), "r"(b[1]));
}
#define NEG4(dst, src) { dst[0]=src[0]^0x80008000u; dst[1]=src[1]^0x80008000u; \
                         dst[2]=src[2]^0x80008000u; dst[3]=src[3]^0x80008000u; }

// ---------------------------------------------------------------------------
// Kernel 1 (R9 config): U/V partials, chunk loop with register prefetch.
// grid (74, 2 c-halves) = 148 CTAs (1/SM), block 256:
// 8 warps = 4 k-slabs(16) x 2 c-sub(32). Chunk ci = s + t*74.
// ---------------------------------------------------------------------------
__global__ __launch_bounds__(256, 1) void k1_partial(
    const float* __restrict__ Qr, const float* __restrict__ Qi,
    const float* __restrict__ re, const float* __restrict__ im, int N)
{
    __shared__ unsigned short sQrh[32][PQ], sQrl[32][PQ], sQih[32][PQ], sQil[32][PQ];
    __shared__ unsigned short sXrh[32][PQ], sXrl[32][PQ], sXih[32][PQ], sXil[32][PQ];

    const int s  = blockIdx.x;
    const int c0 = blockIdx.y * 64;
    const int tid = threadIdx.x;
    const int nchunks = (N + 31) >> 5;
    const float4 f4z = make_float4(0.f, 0.f, 0.f, 0.f);

    const int lane = tid & 31, warp = tid >> 5;
    const int m0 = (warp & 3) * 16;        // k-slab
    const int cs = (warp >> 2) * 32;       // c-sub
    const int r8 = lane & 7, sel = lane >> 3;
    const int atrow = ((sel >> 1) & 1) * 8 + r8;
    const int atcol = m0 + (sel & 1) * 8;
    const int brow = lane & 15;
    const int gid = lane >> 2, tig = lane & 3;

    float u[4][4] = {};
    float v[4][4] = {};

    float4 qa[2], qb[2], xa[2], xb[2];
    auto ldchunk = [&](int ci) {
        #pragma unroll
        for (int q = 0; q < 2; q++) {
            int f = tid + 256 * q;
            int row = f >> 4, k4 = (f & 15) * 4;
            int n = ci * 32 + row;
            bool ok = (n < N);
            qa[q] = ok ? *(const float4*)(Qr + (long)n * 64 + k4) : f4z;
            qb[q] = ok ? *(const float4*)(Qi + (long)n * 64 + k4) : f4z;
            xa[q] = ok ? *(const float4*)(re + (long)n * 128 + c0 + k4) : f4z;
            xb[q] = ok ? *(const float4*)(im + (long)n * 128 + c0 + k4) : f4z;
        }
    };

    ldchunk(s);
    for (int t = 0;; t++) {
        int ci = s + t * NS1;
        if (ci >= nchunks) break;                     // CTA-uniform
        #pragma unroll
        for (int q = 0; q < 2; q++) {
            int f = tid + 256 * q;
            int row = f >> 4, k4 = (f & 15) * 4;
            cvst(&sQrh[row][k4], &sQrl[row][k4], qa[q]);
            cvst(&sQih[row][k4], &sQil[row][k4], qb[q]);
            cvst(&sXrh[row][k4], &sXrl[row][k4], xa[q]);
            cvst(&sXih[row][k4], &sXil[row][k4], xb[q]);
        }
        __syncthreads();
        int cin = ci + NS1;
        if (cin < nchunks) ldchunk(cin);              // prefetch under MMA

        #pragma unroll
        for (int ks = 0; ks < 2; ks++) {
            const int n0k = ks * 16;
            uint32_t qrh[4], qrl[4], qih[4], qil[4], nqh[4], nql[4];
            ldmAT(qrh, sadr(&sQrh[n0k + atrow][atcol]));
            ldmAT(qrl, sadr(&sQrl[n0k + atrow][atcol]));
            ldmAT(qih, sadr(&sQih[n0k + atrow][atcol]));
            ldmAT(qil, sadr(&sQil[n0k + atrow][atcol]));
            NEG4(nqh, qrh);
            NEG4(nql, qrl);
            #pragma unroll
            for (int nt = 0; nt < 4; nt++) {
                uint32_t xh[2], xl[2], yh[2], yl[2];
                ldmBT(xh, sadr(&sXrh[n0k + brow][cs + nt * 8]));
                ldmBT(xl, sadr(&sXrl[n0k + brow][cs + nt * 8]));
                ldmBT(yh, sadr(&sXih[n0k + brow][cs + nt * 8]));
                ldmBT(yl, sadr(&sXil[n0k + brow][cs + nt * 8]));
                mma(u[nt], qrh, xh); mma(u[nt], qrh, xl); mma(u[nt], qrl, xh);
                mma(u[nt], qih, yh); mma(u[nt], qih, yl); mma(u[nt], qil, yh);
                mma(v[nt], qih, xh); mma(v[nt], qih, xl); mma(v[nt], qil, xh);
                mma(v[nt], nqh, yh); mma(v[nt], nqh, yl); mma(v[nt], nql, yh);
            }
        }
        __syncthreads();
    }

    #pragma unroll
    for (int nt = 0; nt < 4; nt++) {
        int k = m0 + gid;
        int c = c0 + cs + nt * 8 + tig * 2;
        *(float2*)&g_part[0][s][k][c]     = make_float2(u[nt][0], u[nt][1]);
        *(float2*)&g_part[0][s][k + 8][c] = make_float2(u[nt][2], u[nt][3]);
        *(float2*)&g_part[1][s][k][c]     = make_float2(v[nt][0], v[nt][1]);
        *(float2*)&g_part[1][s][k + 8][c] = make_float2(v[nt][2], v[nt][3]);
    }
}

// ---------------------------------------------------------------------------
// Kernel 2a: reduce partials over splits, scale row k by TT = Ritz[k]^ld.
// ---------------------------------------------------------------------------
__global__ __launch_bounds__(256) void k2a_reduce(
    const float* __restrict__ Ritz, const int* __restrict__ ldp, int nsplit)
{
    __shared__ float red[256];
    const int o   = threadIdx.x & 31;
    const int seg = threadIdx.x >> 5;
    const int t   = blockIdx.x * 32 + o;       // 0..16383
    const int uv  = t >> 13;
    const int rem = t & 8191;

    const float* p = &g_part[uv][0][0][0] + rem;
    float sum = 0.f;
    for (int s2 = seg; s2 < nsplit; s2 += 8) sum += p[(long)s2 * 8192];
    red[threadIdx.x] = sum;
    __syncthreads();

    if (threadIdx.x < 32) {
        #pragma unroll
        for (int g = 1; g < 8; g++) sum += red[g * 32 + o];
        int k = rem >> 7;
        int ld = *ldp;
        float rz = Ritz[k];
        float tt = 1.f;
        for (int i = 0; i < ld; i++) tt *= rz;
        (&g_UV[0][0][0])[t] = tt * sum;
    }
}

// ---------------------------------------------------------------------------
// Kernel 2b: P = U' @ W, R = V' @ W  ([64,128]@[128,128]); bf16 hi/lo outputs.
// ---------------------------------------------------------------------------
__global__ __launch_bounds__(256) void k2b_pr(const float* __restrict__ W)
{
    __shared__ float sA[64 * 68];
    __shared__ float sW[64 * 64];

    const int m   = blockIdx.x;
    const int cp0 = blockIdx.y * 64;
    const int tx = threadIdx.x, ty = threadIdx.y;
    const int tid = ty * 16 + tx;

    float acc[4][4] = {};

    for (int cc = 0; cc < 128; cc += 64) {
        #pragma unroll
        for (int q = 0; q < 4; q++) {
            int f   = tid + 256 * q;
            int row = f >> 4;
            int c4  = (f & 15) * 4;
            *(float4*)&sA[row * 68 + c4] = *(const float4*)&g_UV[m][row][cc + c4];
            *(float4*)&sW[row * 64 + c4] = *(const float4*)(W + (cc + row) * 128 + cp0 + c4);
        }
        __syncthreads();

        #pragma unroll 4
        for (int r = 0; r < 64; r++) {
            float a[4];
            #pragma unroll
            for (int i = 0; i < 4; i++) a[i] = sA[(ty * 4 + i) * 68 + r];
            float4 w4 = *(float4*)&sW[r * 64 + tx * 4];
            float wj[4] = {w4.x, w4.y, w4.z, w4.w};
            #pragma unroll
            for (int i = 0; i < 4; i++)
                #pragma unroll
                for (int j = 0; j < 4; j++)
                    acc[i][j] += a[i] * wj[j];
        }
        __syncthreads();
    }

    unsigned short (*Dh)[128] = (m == 0) ? g_Ph : g_Rh;
    unsigned short (*Dl)[128] = (m == 0) ? g_Pl : g_Rl;
    #pragma unroll
    for (int i = 0; i < 4; i++) {
        int k = ty * 4 + i;
        int c = cp0 + tx * 4;
        ((uint32_t*)&Dh[k][c])[0] = pk2(acc[i][0], acc[i][1]);
        ((uint32_t*)&Dh[k][c])[1] = pk2(acc[i][2], acc[i][3]);
        float l0 = acc[i][0] - bfr(acc[i][0]), l1 = acc[i][1] - bfr(acc[i][1]);
        float l2 = acc[i][2] - bfr(acc[i][2]), l3 = acc[i][3] - bfr(acc[i][3]);
        ((uint32_t*)&Dl[k][c])[0] = pk2(l0, l1);
        ((uint32_t*)&Dl[k][c])[1] = pk2(l2, l3);
    }
}

// ---------------------------------------------------------------------------
// Kernel 3: res_real = Qr@P + Qi@R, res_imag = Qi@P - Qr@R (MMA 3-pass),
// masked-ReLU epilogue. grid (ceil(N/64), 2 c-halves), block 256:
// 8 warps = 4 n-slabs(16) x 2 c-sub(32).
// Q fully smem-resident (k=64, loaded+converted once). P/R streamed from L2
// in 4 phases of k=16 with register prefetch. Term-major MMA order: same-
// accumulator dependent MMAs spaced by 8 independent ones.
// ---------------------------------------------------------------------------
__global__ __launch_bounds__(256, 2) void k3_out(
    const float* __restrict__ Qr, const float* __restrict__ Qi,
    const float* __restrict__ re, const float* __restrict__ im,
    float* __restrict__ out, int N)
{
    __shared__ unsigned short sQrh[64][PQ], sQrl[64][PQ], sQih[64][PQ], sQil[64][PQ];
    __shared__ unsigned short sPh[16][PQ], sPl[16][PQ], sRh[16][PQ], sRl[16][PQ];

    const int n0 = blockIdx.x * 64;
    const int c0 = blockIdx.y * 64;
    const int tid = threadIdx.x;
    const float4 f4z = make_float4(0.f, 0.f, 0.f, 0.f);

    const int lane = tid & 31, warp = tid >> 5;
    const int m0 = (warp & 3) * 16;           // n-slab
    const int cs = (warp >> 2) * 32;          // c-sub
    const int arow = m0 + (lane & 15);
    const int acol8 = (lane >> 4) * 8;
    const int brow = lane & 15;
    const int gid = lane >> 2, tig = lane & 3;

    // ---- load + convert full Q tile [64 n][64 k] (once) ----
    #pragma unroll
    for (int q = 0; q < 4; q++) {
        int f = tid + 256 * q;
        int row = f >> 4, k4 = (f & 15) * 4;
        int n = n0 + row;
        bool ok = (n < N);
        float4 a = ok ? *(const float4*)(Qr + (long)n * 64 + k4) : f4z;
        float4 b = ok ? *(const float4*)(Qi + (long)n * 64 + k4) : f4z;
        cvst(&sQrh[row][k4], &sQrl[row][k4], a);
        cvst(&sQih[row][k4], &sQil[row][k4], b);
    }

    // P/R phase loaders: 128 threads cover P(hi+lo), 128 cover R(hi+lo).
    const int pf128 = tid & 127;
    const int phalf = tid >> 7;
    const int prow = pf128 >> 3;          // 0..15
    const int pcu  = pf128 & 7;           // 0..7 (x8 halves)
    uint4 vh, vl;
    auto ldPR = [&](int p) {
        int kk = p * 16;
        if (phalf == 0) {
            vh = *(const uint4*)&g_Ph[kk + prow][c0 + pcu * 8];
            vl = *(const uint4*)&g_Pl[kk + prow][c0 + pcu * 8];
        } else {
            vh = *(const uint4*)&g_Rh[kk + prow][c0 + pcu * 8];
            vl = *(const uint4*)&g_Rl[kk + prow][c0 + pcu * 8];
        }
    };
    auto stPR = [&]() {
        if (phalf == 0) {
            *(uint4*)&sPh[prow][pcu * 8] = vh;
            *(uint4*)&sPl[prow][pcu * 8] = vl;
        } else {
            *(uint4*)&sRh[prow][pcu * 8] = vh;
            *(uint4*)&sRl[prow][pcu * 8] = vl;
        }
    };

    float sr[4][4] = {};
    float si[4][4] = {};

    ldPR(0);
    stPR();
    __syncthreads();   // Q + phase-0 P/R visible

    #pragma unroll
    for (int p = 0; p < 4; p++) {
        if (p < 3) ldPR(p + 1);   // L2 prefetch overlaps MMA below

        const int k0 = p * 16;
        uint32_t qrh[4], qrl[4], qih[4], qil[4], nqh[4], nql[4];
        ldmA(qrh, sadr(&sQrh[arow][k0 + acol8]));
        ldmA(qrl, sadr(&sQrl[arow][k0 + acol8]));
        ldmA(qih, sadr(&sQih[arow][k0 + acol8]));
        ldmA(qil, sadr(&sQil[arow][k0 + acol8]));
        NEG4(nqh, qrh);
        NEG4(nql, qrl);

        uint32_t pf[4][2], pl[4][2], rf[4][2], rl2[4][2];
        #pragma unroll
        for (int nt = 0; nt < 4; nt++) {
            ldmBT(pf[nt],  sadr(&sPh[brow][cs + nt * 8]));
            ldmBT(pl[nt],  sadr(&sPl[brow][cs + nt * 8]));
            ldmBT(rf[nt],  sadr(&sRh[brow][cs + nt * 8]));
            ldmBT(rl2[nt], sadr(&sRl[brow][cs + nt * 8]));
        }

        // term-major: dependent MMAs on one accumulator are 8 apart
        #pragma unroll
        for (int nt = 0; nt < 4; nt++) mma(sr[nt], qrh, pf[nt]);
        #pragma unroll
        for (int nt = 0; nt < 4; nt++) mma(si[nt], qih, pf[nt]);
        #pragma unroll
        for (int nt = 0; nt < 4; nt++) mma(sr[nt], qih, rf[nt]);
        #pragma unroll
        for (int nt = 0; nt < 4; nt++) mma(si[nt], nqh, rf[nt]);
        #pragma unroll
        for (int nt = 0; nt < 4; nt++) mma(sr[nt], qrh, pl[nt]);
        #pragma unroll
        for (int nt = 0; nt < 4; nt++) mma(si[nt], qih, pl[nt]);
        #pragma unroll
        for (int nt = 0; nt < 4; nt++) mma(sr[nt], qrl, pf[nt]);
        #pragma unroll
        for (int nt = 0; nt < 4; nt++) mma(si[nt], qil, pf[nt]);
        #pragma unroll
        for (int nt = 0; nt < 4; nt++) mma(sr[nt], qih, rl2[nt]);
        #pragma unroll
        for (int nt = 0; nt < 4; nt++) mma(si[nt], nqh, rl2[nt]);
        #pragma unroll
        for (int nt = 0; nt < 4; nt++) mma(sr[nt], qil, rf[nt]);
        #pragma unroll
        for (int nt = 0; nt < 4; nt++) mma(si[nt], nql, rf[nt]);

        if (p < 3) {
            __syncthreads();    // all warps done reading phase p
            stPR();
            __syncthreads();    // phase p+1 visible
        }
    }

    // epilogue: masked-ReLU add, write out
    const long NC = (long)N * 128;
    #pragma unroll
    for (int nt = 0; nt < 4; nt++) {
        int c = c0 + cs + nt * 8 + tig * 2;
        int r0 = n0 + m0 + gid;
        int r1 = r0 + 8;
        if (r0 < N) {
            long base = (long)r0 * 128 + c;
            float2 rvv = *(const float2*)(re + base);
            float2 ivv = *(const float2*)(im + base);
            float mk0 = (sr[nt][0] >= 0.f) ? 1.f : 0.f;
            float mk1 = (sr[nt][1] >= 0.f) ? 1.f : 0.f;
            *(float2*)(out + base)      = make_float2(rvv.x + mk0 * sr[nt][0], rvv.y + mk1 * sr[nt][1]);
            *(float2*)(out + NC + base) = make_float2(ivv.x + mk0 * si[nt][0], ivv.y + mk1 * si[nt][1]);
        }
        if (r1 < N) {
            long base = (long)r1 * 128 + c;
            float2 rvv = *(const float2*)(re + base);
            float2 ivv = *(const float2*)(im + base);
            float mk2 = (sr[nt][2] >= 0.f) ? 1.f : 0.f;
            float mk3 = (sr[nt][3] >= 0.f) ? 1.f : 0.f;
            *(float2*)(out + base)      = make_float2(rvv.x + mk2 * sr[nt][2], rvv.y + mk3 * sr[nt][3]);
            *(float2*)(out + NC + base) = make_float2(ivv.x + mk2 * si[nt][2], ivv.y + mk3 * si[nt][3]);
        }
    }
}

// ---------------------------------------------------------------------------
extern "C" void kernel_launch(void* const* d_in, const int* in_sizes, int n_in,
                              void* d_out, int out_size)
{
    const float* real  = (const float*)d_in[0];
    const float* imag  = (const float*)d_in[1];
    const float* Qreal = (const float*)d_in[2];
    const float* Qimag = (const float*)d_in[3];
    const float* Ritz  = (const float*)d_in[4];
    const float* W     = (const float*)d_in[5];
    const int*   ldp   = (const int*)d_in[6];
    float* out = (float*)d_out;

    int N = in_sizes[0] / CDIM;
    int nchunks = (N + 31) / 32;
    int nsplit = (nchunks < NS1) ? nchunks : NS1;

    k1_partial<<<dim3(NS1, 2), 256>>>(Qreal, Qimag, real, imag, N);
    k2a_reduce<<<512, 256>>>(Ritz, ldp, nsplit);
    k2b_pr<<<dim3(2, 2), dim3(16, 16)>>>(W);
    k3_out<<<dim3((N + 63) / 64, 2), 256>>>(Qreal, Qimag, real, imag, out, N);
}